// round 11
// baseline (speedup 1.0000x reference)
#include <cuda_runtime.h>
#include <cuda_fp16.h>
#include <cstdint>

#define NN 50000
#define FD 128
#define NR 8
#define NB 4
#define NE 500000
#define KD (NB * FD)  // 512
#define CAP 64

// Scratch (allocation-free rule: __device__ globals)
static __device__ int    g_cnt[NR * NN];                  // 1.6 MB
static __device__ uint2  g_slots[(size_t)NR * NN * CAP];  // 204.8 MB
static __device__ __half g_xh[(size_t)NN * FD];           // 12.8 MB (L2-resident)
static __device__ __half g_zh[(size_t)NN * KD];           // 51.2 MB
static __device__ __half g_wbt[FD * KD];                  // 128 KB, [n][k] transposed

// ---------------------------------------------------------------------------
// Converts: x -> fp16; Wb[k][n] -> fp16 transposed [n][k]
// ---------------------------------------------------------------------------
__global__ void __launch_bounds__(256) convert_x_kernel(const float* __restrict__ x) {
  int t = blockIdx.x * 256 + threadIdx.x;
  if (t >= NN * FD / 4) return;
  float4 v = __ldg(reinterpret_cast<const float4*>(x) + t);
  __half2 lo = __floats2half2_rn(v.x, v.y);
  __half2 hi = __floats2half2_rn(v.z, v.w);
  uint2 o = make_uint2(*reinterpret_cast<uint32_t*>(&lo),
                       *reinterpret_cast<uint32_t*>(&hi));
  reinterpret_cast<uint2*>(g_xh)[t] = o;
}

__global__ void __launch_bounds__(256) convert_wbt_kernel(const float* __restrict__ Wb) {
  int t = blockIdx.x * 256 + threadIdx.x;  // t = n*KD + k
  if (t >= FD * KD) return;
  int n = t >> 9;
  int k = t & 511;
  g_wbt[t] = __float2half_rn(__ldg(Wb + (size_t)k * FD + n));
}

// ---------------------------------------------------------------------------
// Bin: slots[r][dst] <- {src, val}. 8 strided edges per thread (MLP=8).
// ---------------------------------------------------------------------------
#define EPT 8
#define ECHUNK (NE / EPT)  // 62500

__global__ void __launch_bounds__(256) bin_kernel(
    const float* __restrict__ vals, const int* __restrict__ src,
    const int* __restrict__ dst) {
  int e = blockIdx.x * 256 + threadIdx.x;
  if (e >= ECHUNK) return;
  int r = blockIdx.y;
  float v[EPT]; int s[EPT], d[EPT];
#pragma unroll
  for (int q = 0; q < EPT; q++) {
    size_t idx = (size_t)r * NE + e + q * ECHUNK;
    v[q] = __ldg(vals + idx);
    s[q] = __ldg(src + idx);
    d[q] = __ldg(dst + idx);
  }
  int pos[EPT];
#pragma unroll
  for (int q = 0; q < EPT; q++) pos[q] = atomicAdd(&g_cnt[r * NN + d[q]], 1);
#pragma unroll
  for (int q = 0; q < EPT; q++)
    if (pos[q] < CAP)
      g_slots[((size_t)(r * NN + d[q])) * CAP + pos[q]] =
          make_uint2((unsigned)s[q], __float_as_uint(v[q]));
}

// ---------------------------------------------------------------------------
// Gather+mix: FOUR warps per node (2 relations each). Batched lane-load of
// records + register shuffles, 4-wide zero-padded loop (round-7 structure).
// Partials combined via smem; z written fp16 once.
// ---------------------------------------------------------------------------
__device__ __forceinline__ void fma_h4(float4& ra, float v, uint2 xv) {
  float2 lo = __half22float2(*reinterpret_cast<__half2*>(&xv.x));
  float2 hi = __half22float2(*reinterpret_cast<__half2*>(&xv.y));
  ra.x = fmaf(v, lo.x, ra.x); ra.y = fmaf(v, lo.y, ra.y);
  ra.z = fmaf(v, hi.x, ra.z); ra.w = fmaf(v, hi.y, ra.w);
}

__global__ void __launch_bounds__(256, 5) gather_mix_kernel(const float* __restrict__ comp) {
  __shared__ float4 part[2][3][NB][32];  // 12 KB: partials from warps 1-3 of each node
  const int tid = threadIdx.x;
  const int wid = tid >> 5;
  const int lane = tid & 31;
  const int nl = wid >> 2;        // node within block (0..1)
  const int quarter = wid & 3;    // relations quarter*2, quarter*2+1
  const int n = blockIdx.x * 2 + nl;  // NN = 25000*2 exact
  const uint2* xp = reinterpret_cast<const uint2*>(g_xh);

  float4 ab0 = make_float4(0.f, 0.f, 0.f, 0.f);
  float4 ab1 = ab0, ab2 = ab0, ab3 = ab0;

#pragma unroll
  for (int rr = 0; rr < 2; rr++) {
    const int r = quarter * 2 + rr;
    int c = min(__ldg(&g_cnt[r * NN + n]), CAP);
    const uint2* sl = g_slots + (size_t)(r * NN + n) * CAP;
    float4 ra = make_float4(0.f, 0.f, 0.f, 0.f);
    float4 rb = ra;
    for (int base = 0; base < c; base += 32) {
      int m = min(32, c - base);
      uint2 rec = (lane < m) ? __ldg(sl + base + lane) : make_uint2(0u, 0u);
      for (int j = 0; j < m; j += 4) {  // zero-padded: lanes >= m hold {0,0}
        int s0 = __shfl_sync(~0u, rec.x, j);
        int s1 = __shfl_sync(~0u, rec.x, j + 1);
        int s2 = __shfl_sync(~0u, rec.x, j + 2);
        int s3 = __shfl_sync(~0u, rec.x, j + 3);
        float v0 = __uint_as_float(__shfl_sync(~0u, rec.y, j));
        float v1 = __uint_as_float(__shfl_sync(~0u, rec.y, j + 1));
        float v2 = __uint_as_float(__shfl_sync(~0u, rec.y, j + 2));
        float v3 = __uint_as_float(__shfl_sync(~0u, rec.y, j + 3));
        uint2 x0 = __ldg(xp + (size_t)s0 * 32 + lane);
        uint2 x1 = __ldg(xp + (size_t)s1 * 32 + lane);
        uint2 x2 = __ldg(xp + (size_t)s2 * 32 + lane);
        uint2 x3 = __ldg(xp + (size_t)s3 * 32 + lane);
        fma_h4(ra, v0, x0);
        fma_h4(rb, v1, x1);
        fma_h4(ra, v2, x2);
        fma_h4(rb, v3, x3);
      }
    }
    ra.x += rb.x; ra.y += rb.y; ra.z += rb.z; ra.w += rb.w;
    float4 cb = *reinterpret_cast<const float4*>(comp + r * NB);
    ab0.x = fmaf(cb.x, ra.x, ab0.x); ab0.y = fmaf(cb.x, ra.y, ab0.y);
    ab0.z = fmaf(cb.x, ra.z, ab0.z); ab0.w = fmaf(cb.x, ra.w, ab0.w);
    ab1.x = fmaf(cb.y, ra.x, ab1.x); ab1.y = fmaf(cb.y, ra.y, ab1.y);
    ab1.z = fmaf(cb.y, ra.z, ab1.z); ab1.w = fmaf(cb.y, ra.w, ab1.w);
    ab2.x = fmaf(cb.z, ra.x, ab2.x); ab2.y = fmaf(cb.z, ra.y, ab2.y);
    ab2.z = fmaf(cb.z, ra.z, ab2.z); ab2.w = fmaf(cb.z, ra.w, ab2.w);
    ab3.x = fmaf(cb.w, ra.x, ab3.x); ab3.y = fmaf(cb.w, ra.y, ab3.y);
    ab3.z = fmaf(cb.w, ra.z, ab3.z); ab3.w = fmaf(cb.w, ra.w, ab3.w);
  }

  if (quarter > 0) {
    part[nl][quarter - 1][0][lane] = ab0;
    part[nl][quarter - 1][1][lane] = ab1;
    part[nl][quarter - 1][2][lane] = ab2;
    part[nl][quarter - 1][3][lane] = ab3;
  }
  __syncthreads();
  if (quarter == 0) {
#pragma unroll
    for (int w = 0; w < 3; w++) {
      float4 p0 = part[nl][w][0][lane], p1 = part[nl][w][1][lane];
      float4 p2 = part[nl][w][2][lane], p3 = part[nl][w][3][lane];
      ab0.x += p0.x; ab0.y += p0.y; ab0.z += p0.z; ab0.w += p0.w;
      ab1.x += p1.x; ab1.y += p1.y; ab1.z += p1.z; ab1.w += p1.w;
      ab2.x += p2.x; ab2.y += p2.y; ab2.z += p2.z; ab2.w += p2.w;
      ab3.x += p3.x; ab3.y += p3.y; ab3.z += p3.z; ab3.w += p3.w;
    }
    __half* zp = g_zh + (size_t)n * KD + lane * 4;
    float4 ab[4] = {ab0, ab1, ab2, ab3};
#pragma unroll
    for (int b = 0; b < NB; b++) {
      __half2 lo = __floats2half2_rn(ab[b].x, ab[b].y);
      __half2 hi = __floats2half2_rn(ab[b].z, ab[b].w);
      uint2 o = make_uint2(*reinterpret_cast<uint32_t*>(&lo),
                           *reinterpret_cast<uint32_t*>(&hi));
      *reinterpret_cast<uint2*>(zp + b * FD) = o;
    }
  }
}

// ---------------------------------------------------------------------------
// GEMM + relu via fp16 mma.m16n8k16 (fp32 accum), cp.async double-buffered.
// out = relu(z_h[50000,512] @ Wbt_h^T), Wbt stored [n][k].
// ---------------------------------------------------------------------------
#define GBM 128
#define GBK 32
#define TS 40
#define NKIT (KD / GBK)  // 4

#define CP_ASYNC16(saddr, gptr) \
  asm volatile("cp.async.ca.shared.global [%0], [%1], 16;" :: "r"(saddr), "l"(gptr))
#define CP_COMMIT() asm volatile("cp.async.commit_group;")
#define CP_WAIT0() asm volatile("cp.async.wait_group 0;")
#define CP_WAIT1() asm volatile("cp.async.wait_group 1;")

__device__ __forceinline__ void mma_fp16(float* c, const uint32_t* a,
                                         uint32_t b0, uint32_t b1) {
  asm volatile(
      "mma.sync.aligned.m16n8k16.row.col.f32.f16.f16.f32 "
      "{%0,%1,%2,%3}, {%4,%5,%6,%7}, {%8,%9}, {%0,%1,%2,%3};"
      : "+f"(c[0]), "+f"(c[1]), "+f"(c[2]), "+f"(c[3])
      : "r"(a[0]), "r"(a[1]), "r"(a[2]), "r"(a[3]), "r"(b0), "r"(b1));
}

__global__ void __launch_bounds__(256) gemm_relu_kernel(float* __restrict__ C) {
  __shared__ __half As[2][GBM * TS];
  __shared__ __half Bst[2][FD * TS];
  const int tid = threadIdx.x;
  const int lane = tid & 31;
  const int wid = tid >> 5;
  const int g = lane >> 2;
  const int ti = lane & 3;
  const int warp_m = wid >> 1;
  const int warp_n = wid & 1;
  const int m0 = blockIdx.x * GBM;

  // per-thread tile-load coords (2 chunks of 16B for A and for B)
  const int row0_ = tid >> 2, sub0 = tid & 3;
  const int row1_ = (tid + 256) >> 2, sub1 = (tid + 256) & 3;
  const int gmA0 = min(m0 + row0_, NN - 1);  // OOB rows clamp to row 0 area; discarded at store
  const int gmA1 = min(m0 + row1_, NN - 1);

  auto load_tile = [&](int it, int buf) {
    int k0 = it * GBK;
    uint32_t sA = (uint32_t)__cvta_generic_to_shared(&As[buf][row0_ * TS + sub0 * 8]);
    CP_ASYNC16(sA, g_zh + (size_t)gmA0 * KD + k0 + sub0 * 8);
    sA = (uint32_t)__cvta_generic_to_shared(&As[buf][row1_ * TS + sub1 * 8]);
    CP_ASYNC16(sA, g_zh + (size_t)gmA1 * KD + k0 + sub1 * 8);
    uint32_t sB = (uint32_t)__cvta_generic_to_shared(&Bst[buf][row0_ * TS + sub0 * 8]);
    CP_ASYNC16(sB, g_wbt + (size_t)row0_ * KD + k0 + sub0 * 8);
    sB = (uint32_t)__cvta_generic_to_shared(&Bst[buf][row1_ * TS + sub1 * 8]);
    CP_ASYNC16(sB, g_wbt + (size_t)row1_ * KD + k0 + sub1 * 8);
  };

  float acc[2][8][4];
#pragma unroll
  for (int mi = 0; mi < 2; mi++)
#pragma unroll
    for (int nj = 0; nj < 8; nj++)
#pragma unroll
      for (int c = 0; c < 4; c++) acc[mi][nj][c] = 0.f;

  load_tile(0, 0);
  CP_COMMIT();

#pragma unroll
  for (int it = 0; it < NKIT; it++) {
    if (it + 1 < NKIT) {
      load_tile(it + 1, (it + 1) & 1);
      CP_COMMIT();
      CP_WAIT1();
    } else {
      CP_WAIT0();
    }
    __syncthreads();
    const int buf = it & 1;
#pragma unroll
    for (int kk = 0; kk < GBK; kk += 16) {
      uint32_t a[2][4];
#pragma unroll
      for (int mi = 0; mi < 2; mi++) {
        int ar = warp_m * 32 + mi * 16;
        a[mi][0] = *reinterpret_cast<const uint32_t*>(&As[buf][(ar + g) * TS + kk + 2 * ti]);
        a[mi][1] = *reinterpret_cast<const uint32_t*>(&As[buf][(ar + g + 8) * TS + kk + 2 * ti]);
        a[mi][2] = *reinterpret_cast<const uint32_t*>(&As[buf][(ar + g) * TS + kk + 2 * ti + 8]);
        a[mi][3] = *reinterpret_cast<const uint32_t*>(&As[buf][(ar + g + 8) * TS + kk + 2 * ti + 8]);
      }
#pragma unroll
      for (int nj = 0; nj < 8; nj++) {
        int nb = warp_n * 64 + nj * 8 + g;
        uint32_t b0 = *reinterpret_cast<const uint32_t*>(&Bst[buf][nb * TS + kk + 2 * ti]);
        uint32_t b1 = *reinterpret_cast<const uint32_t*>(&Bst[buf][nb * TS + kk + 2 * ti + 8]);
#pragma unroll
        for (int mi = 0; mi < 2; mi++) mma_fp16(acc[mi][nj], a[mi], b0, b1);
      }
    }
    __syncthreads();
  }

#pragma unroll
  for (int mi = 0; mi < 2; mi++) {
#pragma unroll
    for (int nj = 0; nj < 8; nj++) {
      int col = warp_n * 64 + nj * 8 + 2 * ti;
      int row0 = m0 + warp_m * 32 + mi * 16 + g;
      int row1 = row0 + 8;
      if (row0 < NN) {
        float2 o = make_float2(fmaxf(acc[mi][nj][0], 0.f),
                               fmaxf(acc[mi][nj][1], 0.f));
        *reinterpret_cast<float2*>(C + (size_t)row0 * FD + col) = o;
      }
      if (row1 < NN) {
        float2 o = make_float2(fmaxf(acc[mi][nj][2], 0.f),
                               fmaxf(acc[mi][nj][3], 0.f));
        *reinterpret_cast<float2*>(C + (size_t)row1 * FD + col) = o;
      }
    }
  }
}

// ---------------------------------------------------------------------------
extern "C" void kernel_launch(void* const* d_in, const int* in_sizes, int n_in,
                              void* d_out, int out_size) {
  const float* x     = (const float*)d_in[0];
  const float* Wb    = (const float*)d_in[1];
  const float* comp  = (const float*)d_in[2];
  const float* evals = (const float*)d_in[3];
  const int*   esrc  = (const int*)d_in[4];
  const int*   edst  = (const int*)d_in[5];
  float* out = (float*)d_out;

  void* cntp = nullptr;
  cudaGetSymbolAddress(&cntp, g_cnt);
  cudaMemsetAsync(cntp, 0, sizeof(int) * NR * NN, 0);

  convert_x_kernel<<<(NN * FD / 4 + 255) / 256, 256>>>(x);
  convert_wbt_kernel<<<(FD * KD + 255) / 256, 256>>>(Wb);

  dim3 bgrid((ECHUNK + 255) / 256, NR);
  bin_kernel<<<bgrid, 256>>>(evals, esrc, edst);

  gather_mix_kernel<<<NN / 2, 256>>>(comp);  // 25000 blocks, 4 warps/node

  gemm_relu_kernel<<<(NN + GBM - 1) / GBM, 256>>>(out);
}

// round 12
// speedup vs baseline: 1.0904x; 1.0904x over previous
#include <cuda_runtime.h>
#include <cuda_fp16.h>
#include <cstdint>

#define NN 50000
#define FD 128
#define NR 8
#define NB 4
#define NE 500000
#define KD (NB * FD)  // 512
#define CAP 64

// Scratch (allocation-free rule: __device__ globals)
static __device__ int    g_cnt[NR * NN];                  // 1.6 MB
static __device__ uint2  g_slots[(size_t)NR * NN * CAP];  // 204.8 MB
static __device__ __half g_zh[(size_t)NN * KD];           // 51.2 MB
static __device__ __half g_wbt[FD * KD];                  // 128 KB, [n][k] transposed

// ---------------------------------------------------------------------------
// Convert: Wb[k][n] -> fp16 transposed [n][k]
// ---------------------------------------------------------------------------
__global__ void __launch_bounds__(256) convert_wbt_kernel(const float* __restrict__ Wb) {
  int t = blockIdx.x * 256 + threadIdx.x;  // t = n*KD + k
  if (t >= FD * KD) return;
  int n = t >> 9;
  int k = t & 511;
  g_wbt[t] = __float2half_rn(__ldg(Wb + (size_t)k * FD + n));
}

// ---------------------------------------------------------------------------
// Bin: slots[r][dst] <- {src, val}. 8 strided edges per thread (MLP=8).
// ---------------------------------------------------------------------------
#define EPT 8
#define ECHUNK (NE / EPT)  // 62500

__global__ void __launch_bounds__(256) bin_kernel(
    const float* __restrict__ vals, const int* __restrict__ src,
    const int* __restrict__ dst) {
  int e = blockIdx.x * 256 + threadIdx.x;
  if (e >= ECHUNK) return;
  int r = blockIdx.y;
  float v[EPT]; int s[EPT], d[EPT];
#pragma unroll
  for (int q = 0; q < EPT; q++) {
    size_t idx = (size_t)r * NE + e + q * ECHUNK;
    v[q] = __ldg(vals + idx);
    s[q] = __ldg(src + idx);
    d[q] = __ldg(dst + idx);
  }
  int pos[EPT];
#pragma unroll
  for (int q = 0; q < EPT; q++) pos[q] = atomicAdd(&g_cnt[r * NN + d[q]], 1);
#pragma unroll
  for (int q = 0; q < EPT; q++)
    if (pos[q] < CAP)
      g_slots[((size_t)(r * NN + d[q])) * CAP + pos[q]] =
          make_uint2((unsigned)s[q], __float_as_uint(v[q]));
}

// ---------------------------------------------------------------------------
// Gather+mix: TWO warps per node (rels 0-3 / 4-7), round-7 structure.
// fp32 x gather (LDG.128, no cvt on the hot path), register shuffles,
// 4-wide zero-padded loop. Partials via smem; z written fp16 once.
// ---------------------------------------------------------------------------
__device__ __forceinline__ void fma_f4(float4& ra, float v, float4 xv) {
  ra.x = fmaf(v, xv.x, ra.x); ra.y = fmaf(v, xv.y, ra.y);
  ra.z = fmaf(v, xv.z, ra.z); ra.w = fmaf(v, xv.w, ra.w);
}

__global__ void __launch_bounds__(256, 5) gather_mix_kernel(
    const float* __restrict__ x, const float* __restrict__ comp) {
  __shared__ float4 part[4][NB][32];  // 8 KB: warp-B partials
  const int tid = threadIdx.x;
  const int wid = tid >> 5;
  const int lane = tid & 31;
  const int nl = wid >> 1;        // node within block (0..3)
  const int half = wid & 1;       // 0: rel 0-3, 1: rel 4-7
  const int n = blockIdx.x * 4 + nl;  // NN = 12500*4 exact
  const float4* xp = reinterpret_cast<const float4*>(x);  // [node*32 + lane]

  float4 ab0 = make_float4(0.f, 0.f, 0.f, 0.f);
  float4 ab1 = ab0, ab2 = ab0, ab3 = ab0;

#pragma unroll
  for (int rr = 0; rr < 4; rr++) {
    const int r = half * 4 + rr;
    int c = min(__ldg(&g_cnt[r * NN + n]), CAP);
    const uint2* sl = g_slots + (size_t)(r * NN + n) * CAP;
    float4 ra = make_float4(0.f, 0.f, 0.f, 0.f);
    for (int base = 0; base < c; base += 32) {
      int m = min(32, c - base);
      uint2 rec = (lane < m) ? __ldg(sl + base + lane) : make_uint2(0u, 0u);
      for (int j = 0; j < m; j += 4) {  // zero-padded: lanes >= m hold {0,0}
        int s0 = __shfl_sync(~0u, rec.x, j);
        int s1 = __shfl_sync(~0u, rec.x, j + 1);
        int s2 = __shfl_sync(~0u, rec.x, j + 2);
        int s3 = __shfl_sync(~0u, rec.x, j + 3);
        float v0 = __uint_as_float(__shfl_sync(~0u, rec.y, j));
        float v1 = __uint_as_float(__shfl_sync(~0u, rec.y, j + 1));
        float v2 = __uint_as_float(__shfl_sync(~0u, rec.y, j + 2));
        float v3 = __uint_as_float(__shfl_sync(~0u, rec.y, j + 3));
        float4 x0 = __ldg(xp + (size_t)s0 * 32 + lane);
        float4 x1 = __ldg(xp + (size_t)s1 * 32 + lane);
        float4 x2 = __ldg(xp + (size_t)s2 * 32 + lane);
        float4 x3 = __ldg(xp + (size_t)s3 * 32 + lane);
        fma_f4(ra, v0, x0);
        fma_f4(ra, v1, x1);
        fma_f4(ra, v2, x2);
        fma_f4(ra, v3, x3);
      }
    }
    float4 cb = *reinterpret_cast<const float4*>(comp + r * NB);
    ab0.x = fmaf(cb.x, ra.x, ab0.x); ab0.y = fmaf(cb.x, ra.y, ab0.y);
    ab0.z = fmaf(cb.x, ra.z, ab0.z); ab0.w = fmaf(cb.x, ra.w, ab0.w);
    ab1.x = fmaf(cb.y, ra.x, ab1.x); ab1.y = fmaf(cb.y, ra.y, ab1.y);
    ab1.z = fmaf(cb.y, ra.z, ab1.z); ab1.w = fmaf(cb.y, ra.w, ab1.w);
    ab2.x = fmaf(cb.z, ra.x, ab2.x); ab2.y = fmaf(cb.z, ra.y, ab2.y);
    ab2.z = fmaf(cb.z, ra.z, ab2.z); ab2.w = fmaf(cb.z, ra.w, ab2.w);
    ab3.x = fmaf(cb.w, ra.x, ab3.x); ab3.y = fmaf(cb.w, ra.y, ab3.y);
    ab3.z = fmaf(cb.w, ra.z, ab3.z); ab3.w = fmaf(cb.w, ra.w, ab3.w);
  }

  if (half == 1) {
    part[nl][0][lane] = ab0;
    part[nl][1][lane] = ab1;
    part[nl][2][lane] = ab2;
    part[nl][3][lane] = ab3;
  }
  __syncthreads();
  if (half == 0) {
    float4 p0 = part[nl][0][lane], p1 = part[nl][1][lane];
    float4 p2 = part[nl][2][lane], p3 = part[nl][3][lane];
    ab0.x += p0.x; ab0.y += p0.y; ab0.z += p0.z; ab0.w += p0.w;
    ab1.x += p1.x; ab1.y += p1.y; ab1.z += p1.z; ab1.w += p1.w;
    ab2.x += p2.x; ab2.y += p2.y; ab2.z += p2.z; ab2.w += p2.w;
    ab3.x += p3.x; ab3.y += p3.y; ab3.z += p3.z; ab3.w += p3.w;
    __half* zp = g_zh + (size_t)n * KD + lane * 4;
    float4 ab[4] = {ab0, ab1, ab2, ab3};
#pragma unroll
    for (int b = 0; b < NB; b++) {
      __half2 lo = __floats2half2_rn(ab[b].x, ab[b].y);
      __half2 hi = __floats2half2_rn(ab[b].z, ab[b].w);
      uint2 o = make_uint2(*reinterpret_cast<uint32_t*>(&lo),
                           *reinterpret_cast<uint32_t*>(&hi));
      *reinterpret_cast<uint2*>(zp + b * FD) = o;
    }
  }
}

// ---------------------------------------------------------------------------
// GEMM + relu via fp16 mma.m16n8k16 (fp32 accum), cp.async double-buffered.
// out = relu(z_h[50000,512] @ Wbt_h^T), Wbt stored [n][k].
// ---------------------------------------------------------------------------
#define GBM 128
#define GBK 32
#define TS 40
#define NKIT (KD / GBK)  // 4

#define CP_ASYNC16(saddr, gptr) \
  asm volatile("cp.async.ca.shared.global [%0], [%1], 16;" :: "r"(saddr), "l"(gptr))
#define CP_COMMIT() asm volatile("cp.async.commit_group;")
#define CP_WAIT0() asm volatile("cp.async.wait_group 0;")
#define CP_WAIT1() asm volatile("cp.async.wait_group 1;")

__device__ __forceinline__ void mma_fp16(float* c, const uint32_t* a,
                                         uint32_t b0, uint32_t b1) {
  asm volatile(
      "mma.sync.aligned.m16n8k16.row.col.f32.f16.f16.f32 "
      "{%0,%1,%2,%3}, {%4,%5,%6,%7}, {%8,%9}, {%0,%1,%2,%3};"
      : "+f"(c[0]), "+f"(c[1]), "+f"(c[2]), "+f"(c[3])
      : "r"(a[0]), "r"(a[1]), "r"(a[2]), "r"(a[3]), "r"(b0), "r"(b1));
}

__global__ void __launch_bounds__(256) gemm_relu_kernel(float* __restrict__ C) {
  __shared__ __half As[2][GBM * TS];
  __shared__ __half Bst[2][FD * TS];
  const int tid = threadIdx.x;
  const int lane = tid & 31;
  const int wid = tid >> 5;
  const int g = lane >> 2;
  const int ti = lane & 3;
  const int warp_m = wid >> 1;
  const int warp_n = wid & 1;
  const int m0 = blockIdx.x * GBM;

  const int row0_ = tid >> 2, sub0 = tid & 3;
  const int row1_ = (tid + 256) >> 2, sub1 = (tid + 256) & 3;
  const int gmA0 = min(m0 + row0_, NN - 1);  // clamp; clamped rows discarded at store
  const int gmA1 = min(m0 + row1_, NN - 1);

  auto load_tile = [&](int it, int buf) {
    int k0 = it * GBK;
    uint32_t sA = (uint32_t)__cvta_generic_to_shared(&As[buf][row0_ * TS + sub0 * 8]);
    CP_ASYNC16(sA, g_zh + (size_t)gmA0 * KD + k0 + sub0 * 8);
    sA = (uint32_t)__cvta_generic_to_shared(&As[buf][row1_ * TS + sub1 * 8]);
    CP_ASYNC16(sA, g_zh + (size_t)gmA1 * KD + k0 + sub1 * 8);
    uint32_t sB = (uint32_t)__cvta_generic_to_shared(&Bst[buf][row0_ * TS + sub0 * 8]);
    CP_ASYNC16(sB, g_wbt + (size_t)row0_ * KD + k0 + sub0 * 8);
    sB = (uint32_t)__cvta_generic_to_shared(&Bst[buf][row1_ * TS + sub1 * 8]);
    CP_ASYNC16(sB, g_wbt + (size_t)row1_ * KD + k0 + sub1 * 8);
  };

  float acc[2][8][4];
#pragma unroll
  for (int mi = 0; mi < 2; mi++)
#pragma unroll
    for (int nj = 0; nj < 8; nj++)
#pragma unroll
      for (int c = 0; c < 4; c++) acc[mi][nj][c] = 0.f;

  load_tile(0, 0);
  CP_COMMIT();

#pragma unroll
  for (int it = 0; it < NKIT; it++) {
    if (it + 1 < NKIT) {
      load_tile(it + 1, (it + 1) & 1);
      CP_COMMIT();
      CP_WAIT1();
    } else {
      CP_WAIT0();
    }
    __syncthreads();
    const int buf = it & 1;
#pragma unroll
    for (int kk = 0; kk < GBK; kk += 16) {
      uint32_t a[2][4];
#pragma unroll
      for (int mi = 0; mi < 2; mi++) {
        int ar = warp_m * 32 + mi * 16;
        a[mi][0] = *reinterpret_cast<const uint32_t*>(&As[buf][(ar + g) * TS + kk + 2 * ti]);
        a[mi][1] = *reinterpret_cast<const uint32_t*>(&As[buf][(ar + g + 8) * TS + kk + 2 * ti]);
        a[mi][2] = *reinterpret_cast<const uint32_t*>(&As[buf][(ar + g) * TS + kk + 2 * ti + 8]);
        a[mi][3] = *reinterpret_cast<const uint32_t*>(&As[buf][(ar + g + 8) * TS + kk + 2 * ti + 8]);
      }
#pragma unroll
      for (int nj = 0; nj < 8; nj++) {
        int nb = warp_n * 64 + nj * 8 + g;
        uint32_t b0 = *reinterpret_cast<const uint32_t*>(&Bst[buf][nb * TS + kk + 2 * ti]);
        uint32_t b1 = *reinterpret_cast<const uint32_t*>(&Bst[buf][nb * TS + kk + 2 * ti + 8]);
#pragma unroll
        for (int mi = 0; mi < 2; mi++) mma_fp16(acc[mi][nj], a[mi], b0, b1);
      }
    }
    __syncthreads();
  }

#pragma unroll
  for (int mi = 0; mi < 2; mi++) {
#pragma unroll
    for (int nj = 0; nj < 8; nj++) {
      int col = warp_n * 64 + nj * 8 + 2 * ti;
      int row0 = m0 + warp_m * 32 + mi * 16 + g;
      int row1 = row0 + 8;
      if (row0 < NN) {
        float2 o = make_float2(fmaxf(acc[mi][nj][0], 0.f),
                               fmaxf(acc[mi][nj][1], 0.f));
        *reinterpret_cast<float2*>(C + (size_t)row0 * FD + col) = o;
      }
      if (row1 < NN) {
        float2 o = make_float2(fmaxf(acc[mi][nj][2], 0.f),
                               fmaxf(acc[mi][nj][3], 0.f));
        *reinterpret_cast<float2*>(C + (size_t)row1 * FD + col) = o;
      }
    }
  }
}

// ---------------------------------------------------------------------------
extern "C" void kernel_launch(void* const* d_in, const int* in_sizes, int n_in,
                              void* d_out, int out_size) {
  const float* x     = (const float*)d_in[0];
  const float* Wb    = (const float*)d_in[1];
  const float* comp  = (const float*)d_in[2];
  const float* evals = (const float*)d_in[3];
  const int*   esrc  = (const int*)d_in[4];
  const int*   edst  = (const int*)d_in[5];
  float* out = (float*)d_out;

  void* cntp = nullptr;
  cudaGetSymbolAddress(&cntp, g_cnt);
  cudaMemsetAsync(cntp, 0, sizeof(int) * NR * NN, 0);

  convert_wbt_kernel<<<(FD * KD + 255) / 256, 256>>>(Wb);

  dim3 bgrid((ECHUNK + 255) / 256, NR);
  bin_kernel<<<bgrid, 256>>>(evals, esrc, edst);

  gather_mix_kernel<<<NN / 4, 256>>>(x, comp);  // 12500 blocks, 2 warps/node

  gemm_relu_kernel<<<(NN + GBM - 1) / GBM, 256>>>(out);
}